// round 3
// baseline (speedup 1.0000x reference)
#include <cuda_runtime.h>

#define NB 16
#define NH 512
#define NW 512
#define NPIX (NB*NH*NW)
#define NIT 128

// ---------------- device scratch (allocation-free), 16B-aligned for float4 access ----------------
__device__ __align__(16) float2 g_xbar[NPIX];
__device__ __align__(16) float2 g_P1[NPIX];    // dual p1, S-conjugated, layout [b][pw][ph] (digit-reversed)
__device__ __align__(16) float2 g_p2a[NPIX];   // TV dual, h-component, natural layout
__device__ __align__(16) float2 g_p2b[NPIX];   // TV dual, w-component
__device__ __align__(16) float2 g_u1[NPIX];    // rowFFT(S*xbar): [b][h][pw]
__device__ __align__(16) float2 g_T[NPIX];     // after col-iFFT(m*P1): [b][h][pw]
__device__ __align__(16) float2 g_Y[NPIX];     // S*y, permuted to [b][pw][ph]
__device__ __align__(16) float  g_M[NH*NW];    // mask permuted to [pw][ph]
__device__ __align__(16) float2 g_tw[512];     // exp(-2*pi*i*j/512)

#define SIG    ((float)(0.97/3.0))
#define TAU    ((float)(0.97/3.0))
#define INV1PS ((float)(1.0/(1.0+0.97/3.0)))
#define SCL    (0.044194173824159223f)   // 1/sqrt(512)

// ---------------- complex helpers ----------------
__device__ __forceinline__ float2 cadd(float2 a, float2 b){ return make_float2(a.x+b.x, a.y+b.y); }
__device__ __forceinline__ float2 csub(float2 a, float2 b){ return make_float2(a.x-b.x, a.y-b.y); }
__device__ __forceinline__ float2 cmul(float2 a, float2 b){ return make_float2(a.x*b.x - a.y*b.y, a.x*b.y + a.y*b.x); }
__device__ __forceinline__ float2 cmulc(float2 a, float2 b){ return make_float2(a.x*b.x + a.y*b.y, a.y*b.x - a.x*b.y); } // a*conj(b)

template<int S>
__device__ __forceinline__ float2 rot90(float2 z){   // multiply by S*i
    return (S < 0) ? make_float2(z.y, -z.x) : make_float2(-z.y, z.x);
}

// 8-point DFT: X[k] = sum_n x[n] exp(S*2*pi*i*n*k/8), regs in place
template<int S>
__device__ __forceinline__ void dft8(float2 v[8]){
    const float sf = (float)S;
    float2 a0 = cadd(v[0], v[4]), a1 = csub(v[0], v[4]);
    float2 a2 = cadd(v[2], v[6]), a3 = csub(v[2], v[6]);
    float2 a4 = cadd(v[1], v[5]), a5 = csub(v[1], v[5]);
    float2 a6 = cadd(v[3], v[7]), a7 = csub(v[3], v[7]);
    float2 w3 = rot90<S>(a3);
    float2 w7 = rot90<S>(a7);
    float2 E0 = cadd(a0, a2), E2 = csub(a0, a2);
    float2 E1 = cadd(a1, w3), E3 = csub(a1, w3);
    float2 O0 = cadd(a4, a6), O2 = csub(a4, a6);
    float2 O1 = cadd(a5, w7), O3 = csub(a5, w7);
    const float r = 0.7071067811865476f;
    float2 t1 = make_float2(r*(O1.x - sf*O1.y), r*(O1.y + sf*O1.x));
    float2 t2 = rot90<S>(O2);
    float2 t3 = make_float2(r*(-O3.x - sf*O3.y), r*(-O3.y + sf*O3.x));
    v[0]=cadd(E0,O0); v[4]=csub(E0,O0);
    v[1]=cadd(E1,t1); v[5]=csub(E1,t1);
    v[2]=cadd(E2,t2); v[6]=csub(E2,t2);
    v[3]=cadd(E3,t3); v[7]=csub(E3,t3);
}

__device__ __forceinline__ int xpad(int i){ return i + (i >> 3); }
#define EXSZ 576

// 512-pt FFT, 64 threads (t=0..63), 8 complex regs/thread. Unscaled.
// FWD:  in  r[a] = x[t+64a] (natural)      -> out r[j] = X at storage p = 8t+j (digit-reversed)
// !FWD: in  r[j] = data at storage p=8t+j  -> out r[a] = x[t+64a] (natural), sign +1 (times N)
template<bool FWD>
__device__ __forceinline__ void fft512_line(float2 r[8], int t, float2* ex){
    int k0 = t >> 3, m2 = t & 7;
    if (FWD){
        dft8<-1>(r);
        #pragma unroll
        for (int k = 1; k < 8; k++) r[k] = cmul(r[k], g_tw[t*k]);
        __syncthreads();
        #pragma unroll
        for (int k = 0; k < 8; k++) ex[xpad((k<<6) + t)] = r[k];
        __syncthreads();
        #pragma unroll
        for (int m1 = 0; m1 < 8; m1++) r[m1] = ex[xpad((k0<<6) + m2 + (m1<<3))];
        dft8<-1>(r);
        #pragma unroll
        for (int j = 1; j < 8; j++) r[j] = cmul(r[j], g_tw[(m2<<3)*j]);
        __syncthreads();
        #pragma unroll
        for (int j = 0; j < 8; j++) ex[xpad((k0<<6) + (j<<3) + m2)] = r[j];
        __syncthreads();
        #pragma unroll
        for (int j = 0; j < 8; j++) r[j] = ex[xpad((t<<3) + j)];
        dft8<-1>(r);
    } else {
        dft8<1>(r);
        __syncthreads();
        #pragma unroll
        for (int m = 0; m < 8; m++) ex[xpad((t<<3) + m)] = r[m];
        __syncthreads();
        #pragma unroll
        for (int j = 0; j < 8; j++) r[j] = ex[xpad((k0<<6) + (j<<3) + m2)];
        #pragma unroll
        for (int j = 1; j < 8; j++) r[j] = cmulc(r[j], g_tw[(m2<<3)*j]);
        dft8<1>(r);
        __syncthreads();
        #pragma unroll
        for (int m1 = 0; m1 < 8; m1++) ex[xpad((k0<<6) + m2 + (m1<<3))] = r[m1];
        __syncthreads();
        #pragma unroll
        for (int k = 0; k < 8; k++) r[k] = ex[xpad((k<<6) + t)];
        #pragma unroll
        for (int k = 1; k < 8; k++) r[k] = cmulc(r[k], g_tw[t*k]);
        dft8<1>(r);
    }
}

__device__ __forceinline__ int rev8(int p){ return ((p & 7) << 6) | (p & 56) | (p >> 6); }

// ---------------- init kernels ----------------
__global__ void k_tw(){
    int j = threadIdx.x;
    double a = -6.283185307179586476925286766559 * (double)j / 512.0;
    g_tw[j] = make_float2((float)cos(a), (float)sin(a));
}

__global__ void k_init(const float* __restrict__ ir, const float* __restrict__ ii,
                       const float* __restrict__ kr, const float* __restrict__ ki,
                       const int* __restrict__ mask, float2* __restrict__ xout){
    int i = blockIdx.x*256 + threadIdx.x;
    float2 x0 = make_float2(ir[i], ii[i]);
    xout[i] = x0;
    g_xbar[i] = x0;
    float2 z = make_float2(0.f, 0.f);
    g_P1[i] = z; g_p2a[i] = z; g_p2b[i] = z;
    // Y transposed+permuted: i = (b*512 + pw)*512 + ph
    int b = i >> 18, pw = (i >> 9) & 511, ph = i & 511;
    int kh = rev8(ph), kw = rev8(pw);
    float sg = ((kh + kw) & 1) ? -1.f : 1.f;
    int src = (b << 18) | (kh << 9) | kw;
    g_Y[i] = make_float2(sg*kr[src], sg*ki[src]);
    if (i < NH*NW){
        int pw2 = i >> 9, ph2 = i & 511;
        g_M[i] = (float)mask[(rev8(ph2) << 9) | rev8(pw2)];
    }
}

// ---------------- bootstrap: U1 = rowFFT(S*xbar) ----------------
__global__ __launch_bounds__(256) void k_rowF(){
    __shared__ float2 sh_ex[4*EXSZ];
    int tid = threadIdx.x;
    int grp = tid >> 6, t = tid & 63;
    int row = blockIdx.x*4 + grp;         // row = b*512 + h
    int h = row & 511;
    float2* ex = sh_ex + grp*EXSZ;
    float sgn = ((h + t) & 1) ? -1.f : 1.f;
    float2 r[8];
    const float2* src = g_xbar + ((long)row << 9);
    #pragma unroll
    for (int a = 0; a < 8; a++){
        float2 v = src[t + (a<<6)];
        r[a] = make_float2(sgn*v.x, sgn*v.y);
    }
    fft512_line<true>(r, t, ex);
    float2* dst = g_u1 + ((long)row << 9) + (t<<3);
    #pragma unroll
    for (int j = 0; j < 8; j++) dst[j] = make_float2(r[j].x*SCL, r[j].y*SCL);
}

// ---------------- A: TV dual prox ----------------
__global__ __launch_bounds__(256) void k_p2(const float* __restrict__ lam){
    int i = blockIdx.x*256 + threadIdx.x;
    int w = i & 511;
    int h = (i >> 9) & 511;
    float2 xb = g_xbar[i];
    int ih = (i & ~(511<<9)) | (((h+1)&511)<<9);
    int iw = (i & ~511) | ((w+1)&511);
    float2 xh = g_xbar[ih], xw = g_xbar[iw];
    float  L  = lam[i];
    float2 pa = g_p2a[i], pb = g_p2b[i];
    float qax = pa.x + SIG*(xh.x - xb.x);
    float qay = pa.y + SIG*(xh.y - xb.y);
    float qbx = pb.x + SIG*(xw.x - xb.x);
    float qby = pb.y + SIG*(xw.y - xb.y);
    g_p2a[i] = make_float2(fminf(fmaxf(qax,-L),L), fminf(fmaxf(qay,-L),L));
    g_p2b[i] = make_float2(fminf(fmaxf(qbx,-L),L), fminf(fmaxf(qby,-L),L));
}

// ---------------- B: column FFT + P1 prox + column iFFT ----------------
#define CTILE 8
#define CPITCH 9
__global__ __launch_bounds__(512) void k_col(){
    extern __shared__ float2 sm[];
    float2* tile = sm;                         // 512 x CPITCH
    float2* exb  = sm + 512*CPITCH;            // 8 groups x EXSZ
    int tid = threadIdx.x;
    int b  = blockIdx.x >> 6;
    int w0 = (blockIdx.x & 63) * CTILE;
    int g  = tid >> 6, t = tid & 63;
    float2* ex = exb + g*EXSZ;

    // load U1 tile: thread tid loads row hh = tid. Global float4 loads into
    // 16B-aligned staging regs, then float2 stores into pitched shared tile.
    {
        int hh = tid;
        const float4* src = (const float4*)(g_u1 + (((long)(b<<9) + hh) << 9) + w0);
        float4 stg[4];
        #pragma unroll
        for (int q = 0; q < 4; q++) stg[q] = src[q];
        const float2* s2 = (const float2*)stg;
        #pragma unroll
        for (int q = 0; q < 8; q++) tile[hh*CPITCH + q] = s2[q];
    }
    __syncthreads();

    // gather column pw = w0+g into regs (reg a = element h = t+64a)
    float2 r[8];
    #pragma unroll
    for (int a = 0; a < 8; a++) r[a] = tile[(t + (a<<6))*CPITCH + g];

    fft512_line<true>(r, t, ex);   // reg j = u at ph = 8t+j (unscaled)

    // pointwise: P1 prox + mask (all buffers 16B aligned; offsets are 64B multiples)
    {
        int pw = w0 + g;
        long base = (((long)(b<<9) + pw) << 9) + (t<<3);
        float4 p1v[4], yv[4], mv[2];
        const float4* p1p = (const float4*)(g_P1 + base);
        const float4* yp  = (const float4*)(g_Y  + base);
        const float4* mp  = (const float4*)(g_M + ((long)pw << 9) + (t<<3));
        #pragma unroll
        for (int q = 0; q < 4; q++){ p1v[q] = p1p[q]; yv[q] = yp[q]; }
        mv[0] = mp[0]; mv[1] = mp[1];
        const float* m8 = (const float*)mv;
        float4* p1o = (float4*)(g_P1 + base);
        #pragma unroll
        for (int j = 0; j < 8; j++){
            float2 p1 = ((float2*)p1v)[j];
            float2 yy = ((float2*)yv)[j];
            float  m  = m8[j];
            float ux = r[j].x * SCL, uy = r[j].y * SCL;
            float nx = (p1.x + SIG*(m*ux) - SIG*yy.x) * INV1PS;
            float ny = (p1.y + SIG*(m*uy) - SIG*yy.y) * INV1PS;
            ((float2*)p1v)[j] = make_float2(nx, ny);
            r[j] = make_float2(m*nx, m*ny);
        }
        #pragma unroll
        for (int q = 0; q < 4; q++) p1o[q] = p1v[q];
    }

    fft512_line<false>(r, t, ex);  // reg a = element h = t+64a (unscaled)

    // stage result into tile, then coalesced store to g_T
    #pragma unroll
    for (int a = 0; a < 8; a++) tile[(t + (a<<6))*CPITCH + g] = make_float2(r[a].x*SCL, r[a].y*SCL);
    __syncthreads();
    {
        int hh = tid;
        float4 stg[4];
        float2* s2 = (float2*)stg;
        #pragma unroll
        for (int q = 0; q < 8; q++) s2[q] = tile[hh*CPITCH + q];
        float4* dst = (float4*)(g_T + (((long)(b<<9) + hh) << 9) + w0);
        #pragma unroll
        for (int q = 0; q < 4; q++) dst[q] = stg[q];
    }
}

// ---------------- C: row iFFT + primal update + forward row FFT of new xbar ----------------
__global__ __launch_bounds__(256) void k_row(float2* __restrict__ x){
    __shared__ float2 sh_ex[4*EXSZ];
    int tid = threadIdx.x;
    int grp = tid >> 6, t = tid & 63;
    int row = blockIdx.x*4 + grp;          // row = b*512 + h
    int b = row >> 9, h = row & 511;
    float2* ex = sh_ex + grp*EXSZ;

    float4 rstore[4];                      // 16B-aligned backing for r
    float2* r = (float2*)rstore;
    {
        const float4* src = (const float4*)(g_T + ((long)row << 9) + (t<<3));
        #pragma unroll
        for (int q = 0; q < 4; q++) rstore[q] = src[q];
    }
    fft512_line<false>(r, t, ex);          // reg a = v_raw at w = t+64a

    float sgn = ((h + t) & 1) ? -1.f : 1.f;
    float vc = sgn * SCL;

    long rbase = (long)row << 9;
    int hm = (h + 511) & 511;
    long rmbase = ((long)((b<<9) | hm)) << 9;

    float2 xb8[8];
    #pragma unroll
    for (int a = 0; a < 8; a++){
        int w = t + (a<<6);
        int wm = (w + 511) & 511;
        float2 xo = x[rbase + w];
        float2 pam = g_p2a[rmbase + w];
        float2 pac = g_p2a[rbase + w];
        float2 pbm = g_p2b[rbase + wm];
        float2 pbc = g_p2b[rbase + w];
        float divx = (pam.x - pac.x) + (pbm.x - pbc.x);
        float divy = (pam.y - pac.y) + (pbm.y - pbc.y);
        float nx = xo.x - TAU*(vc*r[a].x + divx);
        float ny = xo.y - TAU*(vc*r[a].y + divy);
        x[rbase + w] = make_float2(nx, ny);
        float2 xbv = make_float2(2.f*nx - xo.x, 2.f*ny - xo.y);
        g_xbar[rbase + w] = xbv;
        xb8[a] = make_float2(sgn*xbv.x, sgn*xbv.y);
    }

    #pragma unroll
    for (int a = 0; a < 8; a++) r[a] = xb8[a];
    fft512_line<true>(r, t, ex);
    {
        float2* dst = g_u1 + rbase + (t<<3);
        #pragma unroll
        for (int j = 0; j < 8; j++) dst[j] = make_float2(r[j].x*SCL, r[j].y*SCL);
    }
}

// ---------------- launch ----------------
extern "C" void kernel_launch(void* const* d_in, const int* in_sizes, int n_in,
                              void* d_out, int out_size) {
    const float* ir  = (const float*)d_in[0];
    const float* ii  = (const float*)d_in[1];
    const float* kr  = (const float*)d_in[2];
    const float* ki  = (const float*)d_in[3];
    const float* lam = (const float*)d_in[4];
    const int*   msk = (const int*)  d_in[5];
    float2* x = (float2*)d_out;

    static bool attr_set = false;
    if (!attr_set){
        cudaFuncSetAttribute(k_col, cudaFuncAttributeMaxDynamicSharedMemorySize,
                             (int)((512*CPITCH + 8*EXSZ) * sizeof(float2)));
        attr_set = true;
    }

    k_tw<<<1, 512>>>();
    k_init<<<NPIX/256, 256>>>(ir, ii, kr, ki, msk, x);
    k_rowF<<<(NB*NH)/4, 256>>>();

    for (int it = 0; it < NIT; it++){
        k_p2 <<<NPIX/256, 256>>>(lam);
        k_col<<<NB*64, 512, (512*CPITCH + 8*EXSZ) * sizeof(float2)>>>();
        k_row<<<(NB*NH)/4, 256>>>(x);
    }
}

// round 4
// speedup vs baseline: 1.0089x; 1.0089x over previous
#include <cuda_runtime.h>

#define NB 16
#define NH 512
#define NW 512
#define NPIX (NB*NH*NW)
#define NIT 128

// ---------------- device scratch (allocation-free), 16B-aligned for float4 access ----------------
__device__ __align__(16) float2 g_xbar[NPIX];
__device__ __align__(16) float2 g_P1[NPIX];    // dual p1, S-conjugated, layout [b][pw][ph] (digit-reversed)
__device__ __align__(16) float2 g_p2a[NPIX];   // TV dual, h-component, natural layout
__device__ __align__(16) float2 g_p2b[NPIX];   // TV dual, w-component
__device__ __align__(16) float2 g_u1[NPIX];    // rowFFT(S*xbar): [b][h][pw]
__device__ __align__(16) float2 g_T[NPIX];     // after col-iFFT(m*P1): [b][h][pw]
__device__ __align__(16) float2 g_Y[NPIX];     // S*y, permuted to [b][pw][ph]
__device__ __align__(16) float  g_M[NH*NW];    // mask permuted to [pw][ph]
__device__ __align__(16) float2 g_tw[512];     // exp(-2*pi*i*j/512)

#define SIG    ((float)(0.97/3.0))
#define TAU    ((float)(0.97/3.0))
#define INV1PS ((float)(1.0/(1.0+0.97/3.0)))
#define SCL    (0.044194173824159223f)   // 1/sqrt(512)

// ---------------- complex helpers ----------------
__device__ __forceinline__ float2 cadd(float2 a, float2 b){ return make_float2(a.x+b.x, a.y+b.y); }
__device__ __forceinline__ float2 csub(float2 a, float2 b){ return make_float2(a.x-b.x, a.y-b.y); }
__device__ __forceinline__ float2 cmul(float2 a, float2 b){ return make_float2(a.x*b.x - a.y*b.y, a.x*b.y + a.y*b.x); }
__device__ __forceinline__ float2 cmulc(float2 a, float2 b){ return make_float2(a.x*b.x + a.y*b.y, a.y*b.x - a.x*b.y); } // a*conj(b)

template<int S>
__device__ __forceinline__ float2 rot90(float2 z){   // multiply by S*i
    return (S < 0) ? make_float2(z.y, -z.x) : make_float2(-z.y, z.x);
}

// 8-point DFT: X[k] = sum_n x[n] exp(S*2*pi*i*n*k/8), regs in place
template<int S>
__device__ __forceinline__ void dft8(float2 v[8]){
    const float sf = (float)S;
    float2 a0 = cadd(v[0], v[4]), a1 = csub(v[0], v[4]);
    float2 a2 = cadd(v[2], v[6]), a3 = csub(v[2], v[6]);
    float2 a4 = cadd(v[1], v[5]), a5 = csub(v[1], v[5]);
    float2 a6 = cadd(v[3], v[7]), a7 = csub(v[3], v[7]);
    float2 w3 = rot90<S>(a3);
    float2 w7 = rot90<S>(a7);
    float2 E0 = cadd(a0, a2), E2 = csub(a0, a2);
    float2 E1 = cadd(a1, w3), E3 = csub(a1, w3);
    float2 O0 = cadd(a4, a6), O2 = csub(a4, a6);
    float2 O1 = cadd(a5, w7), O3 = csub(a5, w7);
    const float r = 0.7071067811865476f;
    float2 t1 = make_float2(r*(O1.x - sf*O1.y), r*(O1.y + sf*O1.x));
    float2 t2 = rot90<S>(O2);
    float2 t3 = make_float2(r*(-O3.x - sf*O3.y), r*(-O3.y + sf*O3.x));
    v[0]=cadd(E0,O0); v[4]=csub(E0,O0);
    v[1]=cadd(E1,t1); v[5]=csub(E1,t1);
    v[2]=cadd(E2,t2); v[6]=csub(E2,t2);
    v[3]=cadd(E3,t3); v[7]=csub(E3,t3);
}

__device__ __forceinline__ int xpad(int i){ return i + (i >> 3); }
#define EXSZ 576

// 512-pt FFT, 64 threads (t=0..63), 8 complex regs/thread. Unscaled.
// FWD:  in  r[a] = x[t+64a] (natural)      -> out r[j] = X at storage p = 8t+j (digit-reversed)
// !FWD: in  r[j] = data at storage p=8t+j  -> out r[a] = x[t+64a] (natural), sign +1 (times N)
template<bool FWD>
__device__ __forceinline__ void fft512_line(float2 r[8], int t, float2* ex){
    int k0 = t >> 3, m2 = t & 7;
    if (FWD){
        dft8<-1>(r);
        #pragma unroll
        for (int k = 1; k < 8; k++) r[k] = cmul(r[k], g_tw[t*k]);
        __syncthreads();
        #pragma unroll
        for (int k = 0; k < 8; k++) ex[xpad((k<<6) + t)] = r[k];
        __syncthreads();
        #pragma unroll
        for (int m1 = 0; m1 < 8; m1++) r[m1] = ex[xpad((k0<<6) + m2 + (m1<<3))];
        dft8<-1>(r);
        #pragma unroll
        for (int j = 1; j < 8; j++) r[j] = cmul(r[j], g_tw[(m2<<3)*j]);
        __syncthreads();
        #pragma unroll
        for (int j = 0; j < 8; j++) ex[xpad((k0<<6) + (j<<3) + m2)] = r[j];
        __syncthreads();
        #pragma unroll
        for (int j = 0; j < 8; j++) r[j] = ex[xpad((t<<3) + j)];
        dft8<-1>(r);
    } else {
        dft8<1>(r);
        __syncthreads();
        #pragma unroll
        for (int m = 0; m < 8; m++) ex[xpad((t<<3) + m)] = r[m];
        __syncthreads();
        #pragma unroll
        for (int j = 0; j < 8; j++) r[j] = ex[xpad((k0<<6) + (j<<3) + m2)];
        #pragma unroll
        for (int j = 1; j < 8; j++) r[j] = cmulc(r[j], g_tw[(m2<<3)*j]);
        dft8<1>(r);
        __syncthreads();
        #pragma unroll
        for (int m1 = 0; m1 < 8; m1++) ex[xpad((k0<<6) + m2 + (m1<<3))] = r[m1];
        __syncthreads();
        #pragma unroll
        for (int k = 0; k < 8; k++) r[k] = ex[xpad((k<<6) + t)];
        #pragma unroll
        for (int k = 1; k < 8; k++) r[k] = cmulc(r[k], g_tw[t*k]);
        dft8<1>(r);
    }
}

__device__ __forceinline__ int rev8(int p){ return ((p & 7) << 6) | (p & 56) | (p >> 6); }

// ---------------- init kernels ----------------
__global__ void k_tw(){
    int j = threadIdx.x;
    double a = -6.283185307179586476925286766559 * (double)j / 512.0;
    g_tw[j] = make_float2((float)cos(a), (float)sin(a));
}

__global__ void k_init(const float* __restrict__ ir, const float* __restrict__ ii,
                       const float* __restrict__ kr, const float* __restrict__ ki,
                       const int* __restrict__ mask, float2* __restrict__ xout){
    int i = blockIdx.x*256 + threadIdx.x;
    float2 x0 = make_float2(ir[i], ii[i]);
    xout[i] = x0;
    g_xbar[i] = x0;
    float2 z = make_float2(0.f, 0.f);
    g_P1[i] = z; g_p2a[i] = z; g_p2b[i] = z;
    // Y transposed+permuted: i = (b*512 + pw)*512 + ph
    int b = i >> 18, pw = (i >> 9) & 511, ph = i & 511;
    int kh = rev8(ph), kw = rev8(pw);
    float sg = ((kh + kw) & 1) ? -1.f : 1.f;
    int src = (b << 18) | (kh << 9) | kw;
    g_Y[i] = make_float2(sg*kr[src], sg*ki[src]);
    if (i < NH*NW){
        int pw2 = i >> 9, ph2 = i & 511;
        g_M[i] = (float)mask[(rev8(ph2) << 9) | rev8(pw2)];
    }
}

// ---------------- bootstrap: U1 = rowFFT(S*xbar) ----------------
__global__ __launch_bounds__(256) void k_rowF(){
    __shared__ float2 sh_ex[4*EXSZ];
    int tid = threadIdx.x;
    int grp = tid >> 6, t = tid & 63;
    int row = blockIdx.x*4 + grp;         // row = b*512 + h
    int h = row & 511;
    float2* ex = sh_ex + grp*EXSZ;
    float sgn = ((h + t) & 1) ? -1.f : 1.f;
    float2 r[8];
    const float2* src = g_xbar + ((long)row << 9);
    #pragma unroll
    for (int a = 0; a < 8; a++){
        float2 v = src[t + (a<<6)];
        r[a] = make_float2(sgn*v.x, sgn*v.y);
    }
    fft512_line<true>(r, t, ex);
    float2* dst = g_u1 + ((long)row << 9) + (t<<3);
    #pragma unroll
    for (int j = 0; j < 8; j++) dst[j] = make_float2(r[j].x*SCL, r[j].y*SCL);
}

// ---------------- fused: [col-role] column FFT + P1 prox + column iFFT   (smem tile/exchange OVERLAY)
// ----------------        [p2-role]  TV dual prox (independent of col-role; fills latency bubbles)
#define CTILE 8
#define CPITCH 9
#define COLBLKS (NB*64)                 // 1024
#define P2PX 4
#define P2BLKS (NPIX/(512*P2PX))        // 2048
#define FUSEGRID (COLBLKS + P2BLKS)     // 3072
#define COLSMEM (512*CPITCH*sizeof(float2))   // 36864 B (exchange overlays tile)

__device__ __forceinline__ void col_role(int cb, float2* sm){
    float2* tile = sm;                         // 512 x CPITCH (4608 float2)
    int tid = threadIdx.x;
    int b  = cb >> 6;
    int w0 = (cb & 63) * CTILE;
    int g  = tid >> 6, t = tid & 63;
    float2* ex = sm + g*EXSZ;                  // overlays tile (8*576 = 4608)

    // load U1 tile: thread tid loads row hh = tid (float4 global -> float2 smem, pitched)
    {
        int hh = tid;
        const float4* src = (const float4*)(g_u1 + (((long)(b<<9) + hh) << 9) + w0);
        float4 stg[4];
        #pragma unroll
        for (int q = 0; q < 4; q++) stg[q] = src[q];
        const float2* s2 = (const float2*)stg;
        #pragma unroll
        for (int q = 0; q < 8; q++) tile[hh*CPITCH + q] = s2[q];
    }
    __syncthreads();

    // gather column pw = w0+g into regs (reg a = element h = t+64a)
    float2 r[8];
    #pragma unroll
    for (int a = 0; a < 8; a++) r[a] = tile[(t + (a<<6))*CPITCH + g];
    // tile is dead now; fft's internal pre-store sync fences the aliased exchange writes

    fft512_line<true>(r, t, ex);   // reg j = u at ph = 8t+j (unscaled)

    // pointwise: P1 prox + mask
    {
        int pw = w0 + g;
        long base = (((long)(b<<9) + pw) << 9) + (t<<3);
        float4 p1v[4], yv[4], mv[2];
        const float4* p1p = (const float4*)(g_P1 + base);
        const float4* yp  = (const float4*)(g_Y  + base);
        const float4* mp  = (const float4*)(g_M + ((long)pw << 9) + (t<<3));
        #pragma unroll
        for (int q = 0; q < 4; q++){ p1v[q] = p1p[q]; yv[q] = yp[q]; }
        mv[0] = mp[0]; mv[1] = mp[1];
        const float* m8 = (const float*)mv;
        float4* p1o = (float4*)(g_P1 + base);
        #pragma unroll
        for (int j = 0; j < 8; j++){
            float2 p1 = ((float2*)p1v)[j];
            float2 yy = ((float2*)yv)[j];
            float  m  = m8[j];
            float ux = r[j].x * SCL, uy = r[j].y * SCL;
            float nx = (p1.x + SIG*(m*ux) - SIG*yy.x) * INV1PS;
            float ny = (p1.y + SIG*(m*uy) - SIG*yy.y) * INV1PS;
            ((float2*)p1v)[j] = make_float2(nx, ny);
            r[j] = make_float2(m*nx, m*ny);
        }
        #pragma unroll
        for (int q = 0; q < 4; q++) p1o[q] = p1v[q];
    }

    fft512_line<false>(r, t, ex);  // reg a = element h = t+64a (unscaled)

    __syncthreads();               // all exchange reads done before tile re-staging (overlay)
    #pragma unroll
    for (int a = 0; a < 8; a++) tile[(t + (a<<6))*CPITCH + g] = make_float2(r[a].x*SCL, r[a].y*SCL);
    __syncthreads();
    {
        int hh = tid;
        float4 stg[4];
        float2* s2 = (float2*)stg;
        #pragma unroll
        for (int q = 0; q < 8; q++) s2[q] = tile[hh*CPITCH + q];
        float4* dst = (float4*)(g_T + (((long)(b<<9) + hh) << 9) + w0);
        #pragma unroll
        for (int q = 0; q < 4; q++) dst[q] = stg[q];
    }
}

__device__ __forceinline__ void p2_role(int pid, const float* __restrict__ lam){
    // 4 consecutive pixels per thread, vectorized float4 center loads
    long i0 = (long)pid * (512*P2PX) + (long)threadIdx.x * P2PX;
    int w = (int)(i0 & 511);
    int h = (int)((i0 >> 9) & 511);
    long ih = (i0 & ~((long)511<<9)) | ((long)((h+1)&511)<<9);   // same b,w; row h+1

    float4 xbv[2], xhv[2], pav[2], pbv[2], lav;
    xbv[0] = *(const float4*)(g_xbar + i0);     xbv[1] = *(const float4*)(g_xbar + i0 + 2);
    xhv[0] = *(const float4*)(g_xbar + ih);     xhv[1] = *(const float4*)(g_xbar + ih + 2);
    pav[0] = *(const float4*)(g_p2a + i0);      pav[1] = *(const float4*)(g_p2a + i0 + 2);
    pbv[0] = *(const float4*)(g_p2b + i0);      pbv[1] = *(const float4*)(g_p2b + i0 + 2);
    lav    = *(const float4*)(lam + i0);
    const float2* xb = (const float2*)xbv;
    const float2* xh = (const float2*)xhv;
    float2* pa = (float2*)pav;
    float2* pb = (float2*)pbv;
    const float* L4 = (const float*)&lav;

    #pragma unroll
    for (int k = 0; k < P2PX; k++){
        long iw = (i0 & ~(long)511) | ((w + k + 1) & 511);   // w+1 neighbor (wrap)
        float2 xw = g_xbar[iw];
        float L = L4[k];
        float qax = pa[k].x + SIG*(xh[k].x - xb[k].x);
        float qay = pa[k].y + SIG*(xh[k].y - xb[k].y);
        float qbx = pb[k].x + SIG*(xw.x    - xb[k].x);
        float qby = pb[k].y + SIG*(xw.y    - xb[k].y);
        pa[k] = make_float2(fminf(fmaxf(qax,-L),L), fminf(fmaxf(qay,-L),L));
        pb[k] = make_float2(fminf(fmaxf(qbx,-L),L), fminf(fmaxf(qby,-L),L));
    }
    *(float4*)(g_p2a + i0)     = pav[0];
    *(float4*)(g_p2a + i0 + 2) = pav[1];
    *(float4*)(g_p2b + i0)     = pbv[0];
    *(float4*)(g_p2b + i0 + 2) = pbv[1];
}

__global__ __launch_bounds__(512) void k_fused(const float* __restrict__ lam){
    extern __shared__ float2 sm[];
    int bid = blockIdx.x;
    if (bid % 3 == 0) col_role(bid / 3, sm);
    else              p2_role(bid - bid/3 - 1, lam);
}

// ---------------- C: row iFFT + primal update + forward row FFT of new xbar ----------------
__global__ __launch_bounds__(256) void k_row(float2* __restrict__ x){
    __shared__ float2 sh_ex[4*EXSZ];
    int tid = threadIdx.x;
    int grp = tid >> 6, t = tid & 63;
    int row = blockIdx.x*4 + grp;          // row = b*512 + h
    int b = row >> 9, h = row & 511;
    float2* ex = sh_ex + grp*EXSZ;

    float4 rstore[4];                      // 16B-aligned backing for r
    float2* r = (float2*)rstore;
    {
        const float4* src = (const float4*)(g_T + ((long)row << 9) + (t<<3));
        #pragma unroll
        for (int q = 0; q < 4; q++) rstore[q] = src[q];
    }
    fft512_line<false>(r, t, ex);          // reg a = v_raw at w = t+64a

    float sgn = ((h + t) & 1) ? -1.f : 1.f;
    float vc = sgn * SCL;

    long rbase = (long)row << 9;
    int hm = (h + 511) & 511;
    long rmbase = ((long)((b<<9) | hm)) << 9;

    #pragma unroll
    for (int a = 0; a < 8; a++){
        int w = t + (a<<6);
        int wm = (w + 511) & 511;
        float2 xo = x[rbase + w];
        float2 pam = g_p2a[rmbase + w];
        float2 pac = g_p2a[rbase + w];
        float2 pbm = g_p2b[rbase + wm];
        float2 pbc = g_p2b[rbase + w];
        float divx = (pam.x - pac.x) + (pbm.x - pbc.x);
        float divy = (pam.y - pac.y) + (pbm.y - pbc.y);
        float nx = xo.x - TAU*(vc*r[a].x + divx);
        float ny = xo.y - TAU*(vc*r[a].y + divy);
        x[rbase + w] = make_float2(nx, ny);
        float2 xbv = make_float2(2.f*nx - xo.x, 2.f*ny - xo.y);
        g_xbar[rbase + w] = xbv;
        r[a] = make_float2(sgn*xbv.x, sgn*xbv.y);   // in-place: forward FFT input
    }

    fft512_line<true>(r, t, ex);
    {
        float2* dst = g_u1 + rbase + (t<<3);
        #pragma unroll
        for (int j = 0; j < 8; j++) dst[j] = make_float2(r[j].x*SCL, r[j].y*SCL);
    }
}

// ---------------- launch ----------------
extern "C" void kernel_launch(void* const* d_in, const int* in_sizes, int n_in,
                              void* d_out, int out_size) {
    const float* ir  = (const float*)d_in[0];
    const float* ii  = (const float*)d_in[1];
    const float* kr  = (const float*)d_in[2];
    const float* ki  = (const float*)d_in[3];
    const float* lam = (const float*)d_in[4];
    const int*   msk = (const int*)  d_in[5];
    float2* x = (float2*)d_out;

    static bool attr_set = false;
    if (!attr_set){
        cudaFuncSetAttribute(k_fused, cudaFuncAttributeMaxDynamicSharedMemorySize, (int)COLSMEM);
        attr_set = true;
    }

    k_tw<<<1, 512>>>();
    k_init<<<NPIX/256, 256>>>(ir, ii, kr, ki, msk, x);
    k_rowF<<<(NB*NH)/4, 256>>>();

    for (int it = 0; it < NIT; it++){
        k_fused<<<FUSEGRID, 512, COLSMEM>>>(lam);
        k_row<<<(NB*NH)/4, 256>>>(x);
    }
}

// round 5
// speedup vs baseline: 1.0366x; 1.0274x over previous
#include <cuda_runtime.h>

#define NB 16
#define NH 512
#define NW 512
#define NPIX (NB*NH*NW)
#define NIT 128

// ---------------- device scratch (allocation-free), 16B-aligned for float4 access ----------------
__device__ __align__(16) float2 g_xbar[NPIX];
__device__ __align__(16) float2 g_P1[NPIX];    // dual p1, S-conjugated, layout [b][pw][ph] (digit-reversed)
__device__ __align__(16) float2 g_p2a[NPIX];   // TV dual, h-component, natural layout
__device__ __align__(16) float2 g_p2b[NPIX];   // TV dual, w-component
__device__ __align__(16) float2 g_u1[NPIX];    // rowFFT(S*xbar): [b][h][pw]
__device__ __align__(16) float2 g_T[NPIX];     // after col-iFFT(m*P1): [b][h][pw]
__device__ __align__(16) float2 g_Y[NPIX];     // S*y, permuted to [b][pw][ph]
__device__ __align__(16) float  g_M[NH*NW];    // mask permuted to [pw][ph]
__device__ __align__(16) float2 g_tw[512];     // exp(-2*pi*i*j/512)

#define SIG    ((float)(0.97/3.0))
#define TAU    ((float)(0.97/3.0))
#define INV1PS ((float)(1.0/(1.0+0.97/3.0)))
#define SCL    (0.044194173824159223f)   // 1/sqrt(512)

// ---------------- complex helpers ----------------
__device__ __forceinline__ float2 cadd(float2 a, float2 b){ return make_float2(a.x+b.x, a.y+b.y); }
__device__ __forceinline__ float2 csub(float2 a, float2 b){ return make_float2(a.x-b.x, a.y-b.y); }
__device__ __forceinline__ float2 cmul(float2 a, float2 b){ return make_float2(a.x*b.x - a.y*b.y, a.x*b.y + a.y*b.x); }
__device__ __forceinline__ float2 cmulc(float2 a, float2 b){ return make_float2(a.x*b.x + a.y*b.y, a.y*b.x - a.x*b.y); } // a*conj(b)

template<int S>
__device__ __forceinline__ float2 rot90(float2 z){   // multiply by S*i
    return (S < 0) ? make_float2(z.y, -z.x) : make_float2(-z.y, z.x);
}

// 8-point DFT: X[k] = sum_n x[n] exp(S*2*pi*i*n*k/8), regs in place
template<int S>
__device__ __forceinline__ void dft8(float2 v[8]){
    const float sf = (float)S;
    float2 a0 = cadd(v[0], v[4]), a1 = csub(v[0], v[4]);
    float2 a2 = cadd(v[2], v[6]), a3 = csub(v[2], v[6]);
    float2 a4 = cadd(v[1], v[5]), a5 = csub(v[1], v[5]);
    float2 a6 = cadd(v[3], v[7]), a7 = csub(v[3], v[7]);
    float2 w3 = rot90<S>(a3);
    float2 w7 = rot90<S>(a7);
    float2 E0 = cadd(a0, a2), E2 = csub(a0, a2);
    float2 E1 = cadd(a1, w3), E3 = csub(a1, w3);
    float2 O0 = cadd(a4, a6), O2 = csub(a4, a6);
    float2 O1 = cadd(a5, w7), O3 = csub(a5, w7);
    const float r = 0.7071067811865476f;
    float2 t1 = make_float2(r*(O1.x - sf*O1.y), r*(O1.y + sf*O1.x));
    float2 t2 = rot90<S>(O2);
    float2 t3 = make_float2(r*(-O3.x - sf*O3.y), r*(-O3.y + sf*O3.x));
    v[0]=cadd(E0,O0); v[4]=csub(E0,O0);
    v[1]=cadd(E1,t1); v[5]=csub(E1,t1);
    v[2]=cadd(E2,t2); v[6]=csub(E2,t2);
    v[3]=cadd(E3,t3); v[7]=csub(E3,t3);
}

__device__ __forceinline__ int xpad(int i){ return i + (i >> 3); }
#define EXSZ 576

// 512-pt FFT, 64 threads (t=0..63), 8 complex regs/thread. Unscaled.
// FWD:  in  r[a] = x[t+64a] (natural)      -> out r[j] = X at storage p = 8t+j (digit-reversed)
// !FWD: in  r[j] = data at storage p=8t+j  -> out r[a] = x[t+64a] (natural), sign +1 (times N)
template<bool FWD>
__device__ __forceinline__ void fft512_line(float2 r[8], int t, float2* ex){
    int k0 = t >> 3, m2 = t & 7;
    if (FWD){
        dft8<-1>(r);
        #pragma unroll
        for (int k = 1; k < 8; k++) r[k] = cmul(r[k], g_tw[t*k]);
        __syncthreads();
        #pragma unroll
        for (int k = 0; k < 8; k++) ex[xpad((k<<6) + t)] = r[k];
        __syncthreads();
        #pragma unroll
        for (int m1 = 0; m1 < 8; m1++) r[m1] = ex[xpad((k0<<6) + m2 + (m1<<3))];
        dft8<-1>(r);
        #pragma unroll
        for (int j = 1; j < 8; j++) r[j] = cmul(r[j], g_tw[(m2<<3)*j]);
        __syncthreads();
        #pragma unroll
        for (int j = 0; j < 8; j++) ex[xpad((k0<<6) + (j<<3) + m2)] = r[j];
        __syncthreads();
        #pragma unroll
        for (int j = 0; j < 8; j++) r[j] = ex[xpad((t<<3) + j)];
        dft8<-1>(r);
    } else {
        dft8<1>(r);
        __syncthreads();
        #pragma unroll
        for (int m = 0; m < 8; m++) ex[xpad((t<<3) + m)] = r[m];
        __syncthreads();
        #pragma unroll
        for (int j = 0; j < 8; j++) r[j] = ex[xpad((k0<<6) + (j<<3) + m2)];
        #pragma unroll
        for (int j = 1; j < 8; j++) r[j] = cmulc(r[j], g_tw[(m2<<3)*j]);
        dft8<1>(r);
        __syncthreads();
        #pragma unroll
        for (int m1 = 0; m1 < 8; m1++) ex[xpad((k0<<6) + m2 + (m1<<3))] = r[m1];
        __syncthreads();
        #pragma unroll
        for (int k = 0; k < 8; k++) r[k] = ex[xpad((k<<6) + t)];
        #pragma unroll
        for (int k = 1; k < 8; k++) r[k] = cmulc(r[k], g_tw[t*k]);
        dft8<1>(r);
    }
}

__device__ __forceinline__ int rev8(int p){ return ((p & 7) << 6) | (p & 56) | (p >> 6); }

// ---------------- init kernels ----------------
__global__ void k_tw(){
    int j = threadIdx.x;
    double a = -6.283185307179586476925286766559 * (double)j / 512.0;
    g_tw[j] = make_float2((float)cos(a), (float)sin(a));
}

__global__ void k_init(const float* __restrict__ ir, const float* __restrict__ ii,
                       const float* __restrict__ kr, const float* __restrict__ ki,
                       const int* __restrict__ mask, float2* __restrict__ xout){
    int i = blockIdx.x*256 + threadIdx.x;
    float2 x0 = make_float2(ir[i], ii[i]);
    xout[i] = x0;
    g_xbar[i] = x0;
    float2 z = make_float2(0.f, 0.f);
    g_P1[i] = z; g_p2a[i] = z; g_p2b[i] = z;
    // Y transposed+permuted: i = (b*512 + pw)*512 + ph
    int b = i >> 18, pw = (i >> 9) & 511, ph = i & 511;
    int kh = rev8(ph), kw = rev8(pw);
    float sg = ((kh + kw) & 1) ? -1.f : 1.f;
    int src = (b << 18) | (kh << 9) | kw;
    g_Y[i] = make_float2(sg*kr[src], sg*ki[src]);
    if (i < NH*NW){
        int pw2 = i >> 9, ph2 = i & 511;
        g_M[i] = (float)mask[(rev8(ph2) << 9) | rev8(pw2)];
    }
}

// ---------------- bootstrap: U1 = rowFFT(S*xbar) ----------------
__global__ __launch_bounds__(256) void k_rowF(){
    __shared__ float2 sh_ex[4*EXSZ];
    int tid = threadIdx.x;
    int grp = tid >> 6, t = tid & 63;
    int row = blockIdx.x*4 + grp;         // row = b*512 + h
    int h = row & 511;
    float2* ex = sh_ex + grp*EXSZ;
    float sgn = ((h + t) & 1) ? -1.f : 1.f;
    float2 r[8];
    const float2* src = g_xbar + ((long)row << 9);
    #pragma unroll
    for (int a = 0; a < 8; a++){
        float2 v = src[t + (a<<6)];
        r[a] = make_float2(sgn*v.x, sgn*v.y);
    }
    fft512_line<true>(r, t, ex);
    float2* dst = g_u1 + ((long)row << 9) + (t<<3);
    #pragma unroll
    for (int j = 0; j < 8; j++) dst[j] = make_float2(r[j].x*SCL, r[j].y*SCL);
}

// ---------------- A: TV dual prox (vectorized, 4 px/thread) ----------------
#define P2PX 4
#define P2BLKS (NPIX/(512*P2PX))        // 2048
__global__ __launch_bounds__(512) void k_p2(const float* __restrict__ lam){
    long i0 = (long)blockIdx.x * (512*P2PX) + (long)threadIdx.x * P2PX;
    int w = (int)(i0 & 511);
    int h = (int)((i0 >> 9) & 511);
    long ih = (i0 & ~((long)511<<9)) | ((long)((h+1)&511)<<9);   // same b,w; row h+1

    float4 xbv[2], xhv[2], pav[2], pbv[2], lav;
    xbv[0] = *(const float4*)(g_xbar + i0);     xbv[1] = *(const float4*)(g_xbar + i0 + 2);
    xhv[0] = *(const float4*)(g_xbar + ih);     xhv[1] = *(const float4*)(g_xbar + ih + 2);
    pav[0] = *(const float4*)(g_p2a + i0);      pav[1] = *(const float4*)(g_p2a + i0 + 2);
    pbv[0] = *(const float4*)(g_p2b + i0);      pbv[1] = *(const float4*)(g_p2b + i0 + 2);
    lav    = *(const float4*)(lam + i0);
    const float2* xb = (const float2*)xbv;
    const float2* xh = (const float2*)xhv;
    float2* pa = (float2*)pav;
    float2* pb = (float2*)pbv;
    const float* L4 = (const float*)&lav;

    #pragma unroll
    for (int k = 0; k < P2PX; k++){
        long iw = (i0 & ~(long)511) | ((w + k + 1) & 511);   // w+1 neighbor (wrap)
        float2 xw = g_xbar[iw];
        float L = L4[k];
        float qax = pa[k].x + SIG*(xh[k].x - xb[k].x);
        float qay = pa[k].y + SIG*(xh[k].y - xb[k].y);
        float qbx = pb[k].x + SIG*(xw.x    - xb[k].x);
        float qby = pb[k].y + SIG*(xw.y    - xb[k].y);
        pa[k] = make_float2(fminf(fmaxf(qax,-L),L), fminf(fmaxf(qay,-L),L));
        pb[k] = make_float2(fminf(fmaxf(qbx,-L),L), fminf(fmaxf(qby,-L),L));
    }
    *(float4*)(g_p2a + i0)     = pav[0];
    *(float4*)(g_p2a + i0 + 2) = pav[1];
    *(float4*)(g_p2b + i0)     = pbv[0];
    *(float4*)(g_p2b + i0 + 2) = pbv[1];
}

// ---------------- B: column FFT + P1 prox + column iFFT (tile/exchange smem OVERLAY) ----------------
#define CTILE 8
#define CPITCH 9
#define COLSMEM (512*CPITCH*sizeof(float2))   // 36864 B
__global__ __launch_bounds__(512, 2) void k_col(){
    extern __shared__ float2 sm[];
    float2* tile = sm;                         // 512 x CPITCH (4608 float2)
    int tid = threadIdx.x;
    int b  = blockIdx.x >> 6;
    int w0 = (blockIdx.x & 63) * CTILE;
    int g  = tid >> 6, t = tid & 63;
    float2* ex = sm + g*EXSZ;                  // overlays tile (8*576 = 4608)

    // load U1 tile: thread tid loads row hh = tid (float4 global -> float2 smem, pitched)
    {
        int hh = tid;
        const float4* src = (const float4*)(g_u1 + (((long)(b<<9) + hh) << 9) + w0);
        float4 stg[4];
        #pragma unroll
        for (int q = 0; q < 4; q++) stg[q] = src[q];
        const float2* s2 = (const float2*)stg;
        #pragma unroll
        for (int q = 0; q < 8; q++) tile[hh*CPITCH + q] = s2[q];
    }
    __syncthreads();

    // gather column pw = w0+g into regs (reg a = element h = t+64a)
    float2 r[8];
    #pragma unroll
    for (int a = 0; a < 8; a++) r[a] = tile[(t + (a<<6))*CPITCH + g];
    // tile dead now; fft's pre-store sync fences the aliased exchange writes

    fft512_line<true>(r, t, ex);   // reg j = u at ph = 8t+j (unscaled)

    // pointwise: P1 prox + mask — short live ranges (process per float4 pair)
    {
        int pw = w0 + g;
        long base = (((long)(b<<9) + pw) << 9) + (t<<3);
        const float4* p1p = (const float4*)(g_P1 + base);
        const float4* yp  = (const float4*)(g_Y  + base);
        const float4* mp  = (const float4*)(g_M + ((long)pw << 9) + (t<<3));
        float4* p1o = (float4*)(g_P1 + base);
        float4 mv0 = mp[0], mv1 = mp[1];
        const float* m8a = (const float*)&mv0;
        const float* m8b = (const float*)&mv1;
        #pragma unroll
        for (int q = 0; q < 4; q++){
            float4 p1v = p1p[q];
            float4 yv  = yp[q];
            float m0 = (q < 2) ? m8a[2*q]   : m8b[2*q-4];
            float m1 = (q < 2) ? m8a[2*q+1] : m8b[2*q-3];
            int j = 2*q;
            float nx0 = (p1v.x + SIG*(m0*(r[j].x*SCL))   - SIG*yv.x) * INV1PS;
            float ny0 = (p1v.y + SIG*(m0*(r[j].y*SCL))   - SIG*yv.y) * INV1PS;
            float nx1 = (p1v.z + SIG*(m1*(r[j+1].x*SCL)) - SIG*yv.z) * INV1PS;
            float ny1 = (p1v.w + SIG*(m1*(r[j+1].y*SCL)) - SIG*yv.w) * INV1PS;
            p1o[q] = make_float4(nx0, ny0, nx1, ny1);
            r[j]   = make_float2(m0*nx0, m0*ny0);
            r[j+1] = make_float2(m1*nx1, m1*ny1);
        }
    }

    fft512_line<false>(r, t, ex);  // reg a = element h = t+64a (unscaled)

    __syncthreads();               // all exchange reads done before tile re-staging (overlay)
    #pragma unroll
    for (int a = 0; a < 8; a++) tile[(t + (a<<6))*CPITCH + g] = make_float2(r[a].x*SCL, r[a].y*SCL);
    __syncthreads();
    {
        int hh = tid;
        float4 stg[4];
        float2* s2 = (float2*)stg;
        #pragma unroll
        for (int q = 0; q < 8; q++) s2[q] = tile[hh*CPITCH + q];
        float4* dst = (float4*)(g_T + (((long)(b<<9) + hh) << 9) + w0);
        #pragma unroll
        for (int q = 0; q < 4; q++) dst[q] = stg[q];
    }
}

// ---------------- C: row iFFT + primal update + forward row FFT of new xbar ----------------
__global__ __launch_bounds__(256, 4) void k_row(float2* __restrict__ x){
    __shared__ float2 sh_ex[4*EXSZ];
    int tid = threadIdx.x;
    int grp = tid >> 6, t = tid & 63;
    int row = blockIdx.x*4 + grp;          // row = b*512 + h
    int b = row >> 9, h = row & 511;
    float2* ex = sh_ex + grp*EXSZ;

    float4 rstore[4];                      // 16B-aligned backing for r
    float2* r = (float2*)rstore;
    {
        const float4* src = (const float4*)(g_T + ((long)row << 9) + (t<<3));
        #pragma unroll
        for (int q = 0; q < 4; q++) rstore[q] = src[q];
    }
    fft512_line<false>(r, t, ex);          // reg a = v_raw at w = t+64a

    float sgn = ((h + t) & 1) ? -1.f : 1.f;
    float vc = sgn * SCL;

    long rbase = (long)row << 9;
    int hm = (h + 511) & 511;
    long rmbase = ((long)((b<<9) | hm)) << 9;

    #pragma unroll
    for (int a = 0; a < 8; a++){
        int w = t + (a<<6);
        int wm = (w + 511) & 511;
        float2 xo = x[rbase + w];
        float2 pam = g_p2a[rmbase + w];
        float2 pac = g_p2a[rbase + w];
        float2 pbm = g_p2b[rbase + wm];
        float2 pbc = g_p2b[rbase + w];
        float divx = (pam.x - pac.x) + (pbm.x - pbc.x);
        float divy = (pam.y - pac.y) + (pbm.y - pbc.y);
        float nx = xo.x - TAU*(vc*r[a].x + divx);
        float ny = xo.y - TAU*(vc*r[a].y + divy);
        x[rbase + w] = make_float2(nx, ny);
        float2 xbv = make_float2(2.f*nx - xo.x, 2.f*ny - xo.y);
        g_xbar[rbase + w] = xbv;
        r[a] = make_float2(sgn*xbv.x, sgn*xbv.y);   // in-place: forward FFT input
    }

    fft512_line<true>(r, t, ex);
    {
        float2* dst = g_u1 + rbase + (t<<3);
        #pragma unroll
        for (int j = 0; j < 8; j++) dst[j] = make_float2(r[j].x*SCL, r[j].y*SCL);
    }
}

// ---------------- launch ----------------
extern "C" void kernel_launch(void* const* d_in, const int* in_sizes, int n_in,
                              void* d_out, int out_size) {
    const float* ir  = (const float*)d_in[0];
    const float* ii  = (const float*)d_in[1];
    const float* kr  = (const float*)d_in[2];
    const float* ki  = (const float*)d_in[3];
    const float* lam = (const float*)d_in[4];
    const int*   msk = (const int*)  d_in[5];
    float2* x = (float2*)d_out;

    static bool attr_set = false;
    if (!attr_set){
        cudaFuncSetAttribute(k_col, cudaFuncAttributeMaxDynamicSharedMemorySize, (int)COLSMEM);
        attr_set = true;
    }

    k_tw<<<1, 512>>>();
    k_init<<<NPIX/256, 256>>>(ir, ii, kr, ki, msk, x);
    k_rowF<<<(NB*NH)/4, 256>>>();

    for (int it = 0; it < NIT; it++){
        k_p2 <<<P2BLKS, 512>>>(lam);
        k_col<<<NB*64, 512, COLSMEM>>>();
        k_row<<<(NB*NH)/4, 256>>>(x);
    }
}